// round 10
// baseline (speedup 1.0000x reference)
#include <cuda_runtime.h>

#define S   2048
#define F   512
#define B   32
#define RAD 12
#define KW  25

// ---------------- scratch (device globals: no allocations allowed) ----------
__device__ int   g_i0[S];
__device__ float g_frac[S];

// Gaussian taps (sigma=3, radius=12, normalized) — compile-time immediates
// (fully-unrolled loops index this with constants; ptxas folds to FFMA-imm, rt=1).
__device__ constexpr float KERN[KW] = {
    4.46116e-05f, 1.60100e-04f, 5.14120e-04f, 1.47730e-03f, 3.79880e-03f,
    8.74080e-03f, 1.799760e-02f, 3.316010e-02f, 5.467130e-02f, 8.065920e-02f,
    1.0648560e-01f, 1.2579790e-01f, 1.3298450e-01f, 1.2579790e-01f, 1.0648560e-01f,
    8.065920e-02f, 5.467130e-02f, 3.316010e-02f, 1.799760e-02f, 8.74080e-03f,
    3.79880e-03f, 1.47730e-03f, 5.14120e-04f, 1.60100e-04f, 4.46116e-05f
};

__device__ __forceinline__ int reflect_idx(int r) {
    if (r < 0)       r = -1 - r;
    else if (r >= S) r = 2 * S - 1 - r;
    return r;
}

// ---------------- kernel A: warp precompute + loss (1 block, 256 thr) -------
// Numerics mirror the jax reference bitwise where it matters (see R5):
//  * tt = iota * fl(1/2047); no FMA contraction; sequential ascending dot
//  * softplus = max(w,0) + log1p(exp(-|w|))
//  * cumsum = jax associative_scan pairwise tree (exact rounding pattern)
// Perf: 8 independent per-s accumulator chains (cross-s ILP; per-s op order
// is untouched so results are bitwise identical).
#define WT 256
__global__ void __launch_bounds__(WT) warp_precompute_kernel(
        const float* __restrict__ W1,
        const float* __restrict__ b1,
        const float* __restrict__ W2,
        const float* __restrict__ b2,
        float* __restrict__ out_loss) {
    __shared__ float lev[4095];   // levels 0..11 of the scan tree
    __shared__ float warps[S];
    __shared__ float red[WT];
    __shared__ float sW1[64], sB1[64], sW2[64];
    __shared__ float sB2;

    const int t = threadIdx.x;

    if (t < 64) { sW1[t] = W1[t]; sB1[t] = b1[t]; sW2[t] = W2[t]; }
    if (t == 64) sB2 = b2[0];
    __syncthreads();

    int off[12];
    {
        int o = 0;
        #pragma unroll
        for (int l = 0; l < 12; l++) { off[l] = o; o += (2048 >> l); }
    }

    // ---- elementwise: 8 s-positions per thread, interleaved chains ----
    {
        const float delta = 1.0f / 2047.0f;
        float tt[8], acc[8];
        #pragma unroll
        for (int u = 0; u < 8; u++) {
            int s = t + u * WT;
            tt[u]  = (s == S - 1) ? 1.0f : __fmul_rn((float)s, delta);
            acc[u] = 0.0f;
        }
        for (int j = 0; j < 64; j++) {
            const float w1 = sW1[j], bb = sB1[j], w2 = sW2[j];
            #pragma unroll
            for (int u = 0; u < 8; u++) {
                float h = __fadd_rn(__fmul_rn(tt[u], w1), bb);
                h = fmaxf(h, 0.0f);
                acc[u] = __fadd_rn(acc[u], __fmul_rn(h, w2));
            }
        }
        #pragma unroll
        for (int u = 0; u < 8; u++) {
            float w  = tanhf(__fadd_rn(acc[u], sB2));
            float sp = __fadd_rn(fmaxf(w, 0.0f), log1pf(expf(-fabsf(w))));
            lev[off[0] + t + u * WT] = sp;
        }
    }

    for (int l = 0; l < 11; l++) {
        __syncthreads();
        const float* src = lev + off[l];
        float*       dst = lev + off[l + 1];
        const int n_next = 2048 >> (l + 1);
        for (int k = t; k < n_next; k += WT)
            dst[k] = __fadd_rn(src[2 * k], src[2 * k + 1]);
    }
    __syncthreads();

    for (int l = 10; l >= 0; l--) {
        float*       Ll  = lev + off[l];
        const float* Sl1 = lev + off[l + 1];
        const int half = 2048 >> (l + 1);
        for (int k = t; k < half; k += WT) {
            float odd_val  = Sl1[k];
            float even_val = (k == 0) ? Ll[0] : __fadd_rn(Sl1[k - 1], Ll[2 * k]);
            Ll[2 * k]     = even_val;
            Ll[2 * k + 1] = odd_val;
        }
        __syncthreads();
    }

    const float T = lev[S - 1];

    for (int s = t; s < S; s += WT)
        warps[s] = __fdiv_rn(lev[s], T);
    __syncthreads();

    for (int s = t; s < S; s += WT) {
        float pos = __fmul_rn(warps[s], (float)(S - 1));
        float fi  = floorf(pos);
        fi = fminf(fmaxf(fi, 0.0f), (float)(S - 2));
        int i0 = (int)fi;
        g_i0[s]   = i0;
        g_frac[s] = __fadd_rn(pos, -fi);
    }

    float lsum = 0.0f;
    for (int m = t; m < S - 2; m += WT) {
        float d1a = __fadd_rn(warps[m + 1], -warps[m]);
        float d1b = __fadd_rn(warps[m + 2], -warps[m + 1]);
        float d2  = __fadd_rn(d1b, -d1a);
        lsum = fmaf(d2, d2, lsum);
    }
    red[t] = lsum;
    __syncthreads();
    for (int o2 = WT / 2; o2 > 0; o2 >>= 1) {
        if (t < o2) red[t] += red[t + o2];
        __syncthreads();
    }
    if (t == 0) *out_loss = red[0] / (float)(S - 2);
}

// ---------------- fused smooth + interp -------------------------------------
// Block = 256 threads: two 128-lane halves process alternating CH=8-row conv
// chunks of the needed smoothed range [lo, hi], staged in 68KB dynamic shared,
// then interp + direct write. Interior tiles: reflect-free, all 32 chunk
// inputs preloaded to registers (MLP=32) with immediate-offset LDGs.

#define MAXROWS 136   // >= worst-case span 134
#define CH 8
#define NV (CH + KW - 1)   // 32 values per chunk

__device__ __forceinline__ void conv_math_store(const float* __restrict__ v,
                                                int nvalid,
                                                float* __restrict__ dst128) {
    float acc[CH];
    #pragma unroll
    for (int j = 0; j < CH; j++) acc[j] = 0.0f;
    #pragma unroll
    for (int i = 0; i < NV; i++) {
        #pragma unroll
        for (int j = 0; j < CH; j++) {
            const int k = i - j;
            if (k >= 0 && k < KW)
                acc[j] = fmaf(v[i], KERN[k], acc[j]);
        }
    }
    #pragma unroll
    for (int j = 0; j < CH; j++)
        if (j < nvalid) dst128[j * 128] = acc[j];
}

__global__ void __launch_bounds__(256, 3) fused_kernel(const float* __restrict__ x,
                                                       float* __restrict__ out) {
    extern __shared__ float smrows[];   // MAXROWS * 128 floats

    const int tx   = threadIdx.x;
    const int lane = tx & 127;          // f lane within tile
    const int half = tx >> 7;           // 0 or 1: chunk parity
    const int s0 = blockIdx.x * 32;
    const int f0 = blockIdx.y * 128;
    const int b  = blockIdx.z;

    const int lo = g_i0[s0];
    int hi = g_i0[s0 + 31] + 1;
    if (hi > lo + (MAXROWS - 2)) hi = lo + (MAXROWS - 2);  // defensive only
    const int nrows = hi - lo + 1;

    const float* xb = x + (size_t)b * (S * F) + f0 + lane;
    const bool interior = (lo >= RAD) && (hi + RAD < S);

    if (interior) {
        for (int k = half * CH; k < nrows; k += 2 * CH) {
            const float* p = xb + (size_t)(lo + k - RAD) * F;
            float v[NV];
            #pragma unroll
            for (int i = 0; i < NV; i++) v[i] = __ldg(p + i * F);  // imm offsets
            conv_math_store(v, nrows - k, smrows + k * 128 + lane);
        }
    } else {
        for (int k = half * CH; k < nrows; k += 2 * CH) {
            const int c0 = lo + k;
            float v[NV];
            #pragma unroll
            for (int i = 0; i < NV; i++)
                v[i] = __ldg(xb + (size_t)reflect_idx(c0 - RAD + i) * F);
            conv_math_store(v, nrows - k, smrows + k * 128 + lane);
        }
    }
    __syncthreads();

    // interp: 32 rows x 32 float4-cols; 8 rows per pass, 4 passes
    const int rsub = tx >> 5;     // 0..7
    const int col4 = tx & 31;
    #pragma unroll
    for (int it = 0; it < 4; it++) {
        const int s  = s0 + it * 8 + rsub;
        const int i0 = __ldg(g_i0 + s);
        const float fr = __ldg(g_frac + s);
        const float om = 1.0f - fr;

        const float4 a = ((const float4*)(smrows + (i0 - lo) * 128))[col4];
        const float4 c = ((const float4*)(smrows + (i0 + 1 - lo) * 128))[col4];
        float4 o;
        o.x = a.x * om + c.x * fr;
        o.y = a.y * om + c.y * fr;
        o.z = a.z * om + c.z * fr;
        o.w = a.w * om + c.w * fr;
        ((float4*)(out + ((size_t)(b * S + s) * F + f0)))[col4] = o;
    }
}

// ---------------- launch ----------------------------------------------------
extern "C" void kernel_launch(void* const* d_in, const int* in_sizes, int n_in,
                              void* d_out, int out_size) {
    const float* x  = (const float*)d_in[0];
    const float* W1 = (const float*)d_in[1];
    const float* b1 = (const float*)d_in[2];
    const float* W2 = (const float*)d_in[3];
    const float* b2 = (const float*)d_in[4];
    float* out = (float*)d_out;

    static bool attr_set = false;
    const int smem_bytes = MAXROWS * 128 * sizeof(float);   // 69632
    if (!attr_set) {
        cudaFuncSetAttribute(fused_kernel,
                             cudaFuncAttributeMaxDynamicSharedMemorySize,
                             smem_bytes);
        attr_set = true;
    }

    // loss scalar is the last output element
    warp_precompute_kernel<<<1, WT>>>(W1, b1, W2, b2, out + (out_size - 1));

    dim3 gridF(S / 32, F / 128, B);
    fused_kernel<<<gridF, 256, smem_bytes>>>(x, out);
}

// round 11
// speedup vs baseline: 1.0050x; 1.0050x over previous
#include <cuda_runtime.h>

#define S   2048
#define F   512
#define B   32
#define RAD 12
#define KW  25

// ---------------- scratch (device globals: no allocations allowed) ----------
__device__ int   g_i0[S];
__device__ float g_frac[S];

// Gaussian taps (sigma=3, radius=12, normalized) — compile-time immediates
// (fully-unrolled loops index this with constants; ptxas folds to FFMA-imm, rt=1).
__device__ constexpr float KERN[KW] = {
    4.46116e-05f, 1.60100e-04f, 5.14120e-04f, 1.47730e-03f, 3.79880e-03f,
    8.74080e-03f, 1.799760e-02f, 3.316010e-02f, 5.467130e-02f, 8.065920e-02f,
    1.0648560e-01f, 1.2579790e-01f, 1.3298450e-01f, 1.2579790e-01f, 1.0648560e-01f,
    8.065920e-02f, 5.467130e-02f, 3.316010e-02f, 1.799760e-02f, 8.74080e-03f,
    3.79880e-03f, 1.47730e-03f, 5.14120e-04f, 1.60100e-04f, 4.46116e-05f
};

__device__ __forceinline__ int reflect_idx(int r) {
    if (r < 0)       r = -1 - r;
    else if (r >= S) r = 2 * S - 1 - r;
    return r;
}

// ---------------- kernel A: warp precompute + loss (1 block, 256 thr) -------
// Numerics mirror the jax reference bitwise where it matters (see R5):
//  * tt = iota * fl(1/2047); no FMA contraction; sequential ascending dot
//  * softplus = max(w,0) + log1p(exp(-|w|))
//  * cumsum = jax associative_scan pairwise tree (exact rounding pattern)
// Perf: 8 independent per-s accumulator chains (cross-s ILP; per-s op order
// is untouched so results are bitwise identical).
#define WT 256
__global__ void __launch_bounds__(WT) warp_precompute_kernel(
        const float* __restrict__ W1,
        const float* __restrict__ b1,
        const float* __restrict__ W2,
        const float* __restrict__ b2,
        float* __restrict__ out_loss) {
    __shared__ float lev[4095];   // levels 0..11 of the scan tree
    __shared__ float warps[S];
    __shared__ float red[WT];
    __shared__ float sW1[64], sB1[64], sW2[64];
    __shared__ float sB2;

    const int t = threadIdx.x;

    if (t < 64) { sW1[t] = W1[t]; sB1[t] = b1[t]; sW2[t] = W2[t]; }
    if (t == 64) sB2 = b2[0];
    __syncthreads();

    int off[12];
    {
        int o = 0;
        #pragma unroll
        for (int l = 0; l < 12; l++) { off[l] = o; o += (2048 >> l); }
    }

    // ---- elementwise: 8 s-positions per thread, interleaved chains ----
    {
        const float delta = 1.0f / 2047.0f;
        float tt[8], acc[8];
        #pragma unroll
        for (int u = 0; u < 8; u++) {
            int s = t + u * WT;
            tt[u]  = (s == S - 1) ? 1.0f : __fmul_rn((float)s, delta);
            acc[u] = 0.0f;
        }
        for (int j = 0; j < 64; j++) {
            const float w1 = sW1[j], bb = sB1[j], w2 = sW2[j];
            #pragma unroll
            for (int u = 0; u < 8; u++) {
                float h = __fadd_rn(__fmul_rn(tt[u], w1), bb);
                h = fmaxf(h, 0.0f);
                acc[u] = __fadd_rn(acc[u], __fmul_rn(h, w2));
            }
        }
        #pragma unroll
        for (int u = 0; u < 8; u++) {
            float w  = tanhf(__fadd_rn(acc[u], sB2));
            float sp = __fadd_rn(fmaxf(w, 0.0f), log1pf(expf(-fabsf(w))));
            lev[off[0] + t + u * WT] = sp;
        }
    }

    for (int l = 0; l < 11; l++) {
        __syncthreads();
        const float* src = lev + off[l];
        float*       dst = lev + off[l + 1];
        const int n_next = 2048 >> (l + 1);
        for (int k = t; k < n_next; k += WT)
            dst[k] = __fadd_rn(src[2 * k], src[2 * k + 1]);
    }
    __syncthreads();

    for (int l = 10; l >= 0; l--) {
        float*       Ll  = lev + off[l];
        const float* Sl1 = lev + off[l + 1];
        const int half = 2048 >> (l + 1);
        for (int k = t; k < half; k += WT) {
            float odd_val  = Sl1[k];
            float even_val = (k == 0) ? Ll[0] : __fadd_rn(Sl1[k - 1], Ll[2 * k]);
            Ll[2 * k]     = even_val;
            Ll[2 * k + 1] = odd_val;
        }
        __syncthreads();
    }

    const float T = lev[S - 1];

    for (int s = t; s < S; s += WT)
        warps[s] = __fdiv_rn(lev[s], T);
    __syncthreads();

    for (int s = t; s < S; s += WT) {
        float pos = __fmul_rn(warps[s], (float)(S - 1));
        float fi  = floorf(pos);
        fi = fminf(fmaxf(fi, 0.0f), (float)(S - 2));
        int i0 = (int)fi;
        g_i0[s]   = i0;
        g_frac[s] = __fadd_rn(pos, -fi);
    }

    float lsum = 0.0f;
    for (int m = t; m < S - 2; m += WT) {
        float d1a = __fadd_rn(warps[m + 1], -warps[m]);
        float d1b = __fadd_rn(warps[m + 2], -warps[m + 1]);
        float d2  = __fadd_rn(d1b, -d1a);
        lsum = fmaf(d2, d2, lsum);
    }
    red[t] = lsum;
    __syncthreads();
    for (int o2 = WT / 2; o2 > 0; o2 >>= 1) {
        if (t < o2) red[t] += red[t + o2];
        __syncthreads();
    }
    if (t == 0) *out_loss = red[0] / (float)(S - 2);
}

// ---------------- fused smooth + interp -------------------------------------
// Block = 256 threads: two 128-lane halves process alternating CH=8-row conv
// chunks of the needed smoothed range [lo, hi], staged in 68KB dynamic shared,
// then interp + direct write. Interior tiles: reflect-free, all 32 chunk
// inputs preloaded to registers (MLP=32) with immediate-offset LDGs.

#define MAXROWS 136   // >= worst-case span 134
#define CH 8
#define NV (CH + KW - 1)   // 32 values per chunk

__device__ __forceinline__ void conv_math_store(const float* __restrict__ v,
                                                int nvalid,
                                                float* __restrict__ dst128) {
    float acc[CH];
    #pragma unroll
    for (int j = 0; j < CH; j++) acc[j] = 0.0f;
    #pragma unroll
    for (int i = 0; i < NV; i++) {
        #pragma unroll
        for (int j = 0; j < CH; j++) {
            const int k = i - j;
            if (k >= 0 && k < KW)
                acc[j] = fmaf(v[i], KERN[k], acc[j]);
        }
    }
    #pragma unroll
    for (int j = 0; j < CH; j++)
        if (j < nvalid) dst128[j * 128] = acc[j];
}

__global__ void __launch_bounds__(256, 3) fused_kernel(const float* __restrict__ x,
                                                       float* __restrict__ out) {
    extern __shared__ float smrows[];   // MAXROWS * 128 floats

    const int tx   = threadIdx.x;
    const int lane = tx & 127;          // f lane within tile
    const int half = tx >> 7;           // 0 or 1: chunk parity
    const int s0 = blockIdx.x * 32;
    const int f0 = blockIdx.y * 128;
    const int b  = blockIdx.z;

    const int lo = g_i0[s0];
    int hi = g_i0[s0 + 31] + 1;
    if (hi > lo + (MAXROWS - 2)) hi = lo + (MAXROWS - 2);  // defensive only
    const int nrows = hi - lo + 1;

    const float* xb = x + (size_t)b * (S * F) + f0 + lane;
    const bool interior = (lo >= RAD) && (hi + RAD < S);

    if (interior) {
        for (int k = half * CH; k < nrows; k += 2 * CH) {
            const float* p = xb + (size_t)(lo + k - RAD) * F;
            float v[NV];
            #pragma unroll
            for (int i = 0; i < NV; i++) v[i] = __ldg(p + i * F);  // imm offsets
            conv_math_store(v, nrows - k, smrows + k * 128 + lane);
        }
    } else {
        for (int k = half * CH; k < nrows; k += 2 * CH) {
            const int c0 = lo + k;
            float v[NV];
            #pragma unroll
            for (int i = 0; i < NV; i++)
                v[i] = __ldg(xb + (size_t)reflect_idx(c0 - RAD + i) * F);
            conv_math_store(v, nrows - k, smrows + k * 128 + lane);
        }
    }
    __syncthreads();

    // interp: 32 rows x 32 float4-cols; 8 rows per pass, 4 passes
    const int rsub = tx >> 5;     // 0..7
    const int col4 = tx & 31;
    #pragma unroll
    for (int it = 0; it < 4; it++) {
        const int s  = s0 + it * 8 + rsub;
        const int i0 = __ldg(g_i0 + s);
        const float fr = __ldg(g_frac + s);
        const float om = 1.0f - fr;

        const float4 a = ((const float4*)(smrows + (i0 - lo) * 128))[col4];
        const float4 c = ((const float4*)(smrows + (i0 + 1 - lo) * 128))[col4];
        float4 o;
        o.x = a.x * om + c.x * fr;
        o.y = a.y * om + c.y * fr;
        o.z = a.z * om + c.z * fr;
        o.w = a.w * om + c.w * fr;
        ((float4*)(out + ((size_t)(b * S + s) * F + f0)))[col4] = o;
    }
}

// ---------------- launch ----------------------------------------------------
extern "C" void kernel_launch(void* const* d_in, const int* in_sizes, int n_in,
                              void* d_out, int out_size) {
    const float* x  = (const float*)d_in[0];
    const float* W1 = (const float*)d_in[1];
    const float* b1 = (const float*)d_in[2];
    const float* W2 = (const float*)d_in[3];
    const float* b2 = (const float*)d_in[4];
    float* out = (float*)d_out;

    static bool attr_set = false;
    const int smem_bytes = MAXROWS * 128 * sizeof(float);   // 69632
    if (!attr_set) {
        cudaFuncSetAttribute(fused_kernel,
                             cudaFuncAttributeMaxDynamicSharedMemorySize,
                             smem_bytes);
        attr_set = true;
    }

    // loss scalar is the last output element
    warp_precompute_kernel<<<1, WT>>>(W1, b1, W2, b2, out + (out_size - 1));

    dim3 gridF(S / 32, F / 128, B);
    fused_kernel<<<gridF, 256, smem_bytes>>>(x, out);
}

// round 12
// speedup vs baseline: 1.1246x; 1.1190x over previous
#include <cuda_runtime.h>

#define S   2048
#define F   512
#define B   32
#define RAD 12
#define KW  25

// ---------------- scratch (device globals: no allocations allowed) ----------
__device__ int   g_i0[S];
__device__ float g_frac[S];

// Gaussian taps (sigma=3, radius=12, normalized) — compile-time immediates
// (fully-unrolled loops index this with constants; ptxas folds to FFMA-imm, rt=1).
__device__ constexpr float KERN[KW] = {
    4.46116e-05f, 1.60100e-04f, 5.14120e-04f, 1.47730e-03f, 3.79880e-03f,
    8.74080e-03f, 1.799760e-02f, 3.316010e-02f, 5.467130e-02f, 8.065920e-02f,
    1.0648560e-01f, 1.2579790e-01f, 1.3298450e-01f, 1.2579790e-01f, 1.0648560e-01f,
    8.065920e-02f, 5.467130e-02f, 3.316010e-02f, 1.799760e-02f, 8.74080e-03f,
    3.79880e-03f, 1.47730e-03f, 5.14120e-04f, 1.60100e-04f, 4.46116e-05f
};

__device__ __forceinline__ int reflect_idx(int r) {
    if (r < 0)       r = -1 - r;
    else if (r >= S) r = 2 * S - 1 - r;
    return r;
}

// ---------------- kernel A: warp precompute + loss (1 block, 256 thr) -------
// Numerics mirror the jax reference bitwise where it matters (see R5):
//  * tt = iota * fl(1/2047); no FMA contraction; sequential ascending dot
//  * softplus = max(w,0) + log1p(exp(-|w|))
//  * cumsum = jax associative_scan pairwise tree (exact rounding pattern)
#define WT 256
__global__ void __launch_bounds__(WT) warp_precompute_kernel(
        const float* __restrict__ W1,
        const float* __restrict__ b1,
        const float* __restrict__ W2,
        const float* __restrict__ b2,
        float* __restrict__ out_loss) {
    __shared__ float lev[4095];   // levels 0..11 of the scan tree
    __shared__ float warps[S];
    __shared__ float red[WT];
    __shared__ float sW1[64], sB1[64], sW2[64];
    __shared__ float sB2;

    const int t = threadIdx.x;

    if (t < 64) { sW1[t] = W1[t]; sB1[t] = b1[t]; sW2[t] = W2[t]; }
    if (t == 64) sB2 = b2[0];
    __syncthreads();

    int off[12];
    {
        int o = 0;
        #pragma unroll
        for (int l = 0; l < 12; l++) { off[l] = o; o += (2048 >> l); }
    }

    // ---- elementwise: 8 s-positions per thread, interleaved chains ----
    {
        const float delta = 1.0f / 2047.0f;
        float tt[8], acc[8];
        #pragma unroll
        for (int u = 0; u < 8; u++) {
            int s = t + u * WT;
            tt[u]  = (s == S - 1) ? 1.0f : __fmul_rn((float)s, delta);
            acc[u] = 0.0f;
        }
        for (int j = 0; j < 64; j++) {
            const float w1 = sW1[j], bb = sB1[j], w2 = sW2[j];
            #pragma unroll
            for (int u = 0; u < 8; u++) {
                float h = __fadd_rn(__fmul_rn(tt[u], w1), bb);
                h = fmaxf(h, 0.0f);
                acc[u] = __fadd_rn(acc[u], __fmul_rn(h, w2));
            }
        }
        #pragma unroll
        for (int u = 0; u < 8; u++) {
            float w  = tanhf(__fadd_rn(acc[u], sB2));
            float sp = __fadd_rn(fmaxf(w, 0.0f), log1pf(expf(-fabsf(w))));
            lev[off[0] + t + u * WT] = sp;
        }
    }

    for (int l = 0; l < 11; l++) {
        __syncthreads();
        const float* src = lev + off[l];
        float*       dst = lev + off[l + 1];
        const int n_next = 2048 >> (l + 1);
        for (int k = t; k < n_next; k += WT)
            dst[k] = __fadd_rn(src[2 * k], src[2 * k + 1]);
    }
    __syncthreads();

    for (int l = 10; l >= 0; l--) {
        float*       Ll  = lev + off[l];
        const float* Sl1 = lev + off[l + 1];
        const int half = 2048 >> (l + 1);
        for (int k = t; k < half; k += WT) {
            float odd_val  = Sl1[k];
            float even_val = (k == 0) ? Ll[0] : __fadd_rn(Sl1[k - 1], Ll[2 * k]);
            Ll[2 * k]     = even_val;
            Ll[2 * k + 1] = odd_val;
        }
        __syncthreads();
    }

    const float T = lev[S - 1];

    for (int s = t; s < S; s += WT)
        warps[s] = __fdiv_rn(lev[s], T);
    __syncthreads();

    for (int s = t; s < S; s += WT) {
        float pos = __fmul_rn(warps[s], (float)(S - 1));
        float fi  = floorf(pos);
        fi = fminf(fmaxf(fi, 0.0f), (float)(S - 2));
        int i0 = (int)fi;
        g_i0[s]   = i0;
        g_frac[s] = __fadd_rn(pos, -fi);
    }

    float lsum = 0.0f;
    for (int m = t; m < S - 2; m += WT) {
        float d1a = __fadd_rn(warps[m + 1], -warps[m]);
        float d1b = __fadd_rn(warps[m + 2], -warps[m + 1]);
        float d2  = __fadd_rn(d1b, -d1a);
        lsum = fmaf(d2, d2, lsum);
    }
    red[t] = lsum;
    __syncthreads();
    for (int o2 = WT / 2; o2 > 0; o2 >>= 1) {
        if (t < o2) red[t] += red[t + o2];
        __syncthreads();
    }
    if (t == 0) *out_loss = red[0] / (float)(S - 2);
}

// ---------------- fused smooth + interp -------------------------------------
// Block = 256 threads = 4 quarters x 64 f-lanes. Quarters take alternating
// CH=8-row conv chunks of the needed smoothed range [lo, hi] (monotone warp
// => span <= 134), staged in 34KB dynamic shared (5 blocks/SM, 40 warps),
// then interp + direct write. Interior tiles: reflect-free immediate-offset
// loads, split 16+16 to bound register liveness.

#define MAXROWS 136
#define CH 8
#define NV (CH + KW - 1)   // 32 values per chunk
#define FL 64              // f-lanes per block

__device__ __forceinline__ void conv_math_store(const float* __restrict__ v,
                                                int nvalid,
                                                float* __restrict__ dst) {
    float acc[CH];
    #pragma unroll
    for (int j = 0; j < CH; j++) acc[j] = 0.0f;
    #pragma unroll
    for (int i = 0; i < NV; i++) {
        #pragma unroll
        for (int j = 0; j < CH; j++) {
            const int k = i - j;
            if (k >= 0 && k < KW)
                acc[j] = fmaf(v[i], KERN[k], acc[j]);
        }
    }
    #pragma unroll
    for (int j = 0; j < CH; j++)
        if (j < nvalid) dst[j * FL] = acc[j];
}

__global__ void __launch_bounds__(256, 5) fused_kernel(const float* __restrict__ x,
                                                       float* __restrict__ out) {
    extern __shared__ float smrows[];   // MAXROWS * FL floats

    const int tx      = threadIdx.x;
    const int lane    = tx & (FL - 1);  // f lane within tile
    const int quarter = tx >> 6;        // 0..3: chunk parity
    const int s0 = blockIdx.x * 32;
    const int f0 = blockIdx.y * FL;
    const int b  = blockIdx.z;

    const int lo = g_i0[s0];
    int hi = g_i0[s0 + 31] + 1;
    if (hi > lo + (MAXROWS - 2)) hi = lo + (MAXROWS - 2);  // defensive only
    const int nrows = hi - lo + 1;

    const float* xb = x + (size_t)b * (S * F) + f0 + lane;
    const bool interior = (lo >= RAD) && (hi + RAD < S);

    if (interior) {
        for (int k = quarter * CH; k < nrows; k += 4 * CH) {
            const float* p = xb + (size_t)(lo + k - RAD) * F;
            float v[NV];
            #pragma unroll
            for (int i = 0; i < 16; i++) v[i] = __ldg(p + i * F);
            #pragma unroll
            for (int i = 16; i < NV; i++) v[i] = __ldg(p + i * F);
            conv_math_store(v, nrows - k, smrows + k * FL + lane);
        }
    } else {
        for (int k = quarter * CH; k < nrows; k += 4 * CH) {
            const int c0 = lo + k;
            float v[NV];
            #pragma unroll
            for (int i = 0; i < NV; i++)
                v[i] = __ldg(xb + (size_t)reflect_idx(c0 - RAD + i) * F);
            conv_math_store(v, nrows - k, smrows + k * FL + lane);
        }
    }
    __syncthreads();

    // interp: 32 rows x 16 float4-cols; 16 rows per pass, 2 passes
    const int rsub = tx >> 4;     // 0..15
    const int col4 = tx & 15;
    #pragma unroll
    for (int it = 0; it < 2; it++) {
        const int s  = s0 + it * 16 + rsub;
        const int i0 = __ldg(g_i0 + s);
        const float fr = __ldg(g_frac + s);
        const float om = 1.0f - fr;

        const float4 a = ((const float4*)(smrows + (i0 - lo) * FL))[col4];
        const float4 c = ((const float4*)(smrows + (i0 + 1 - lo) * FL))[col4];
        float4 o;
        o.x = a.x * om + c.x * fr;
        o.y = a.y * om + c.y * fr;
        o.z = a.z * om + c.z * fr;
        o.w = a.w * om + c.w * fr;
        ((float4*)(out + ((size_t)(b * S + s) * F + f0)))[col4] = o;
    }
}

// ---------------- launch ----------------------------------------------------
extern "C" void kernel_launch(void* const* d_in, const int* in_sizes, int n_in,
                              void* d_out, int out_size) {
    const float* x  = (const float*)d_in[0];
    const float* W1 = (const float*)d_in[1];
    const float* b1 = (const float*)d_in[2];
    const float* W2 = (const float*)d_in[3];
    const float* b2 = (const float*)d_in[4];
    float* out = (float*)d_out;

    const int smem_bytes = MAXROWS * FL * sizeof(float);   // 34816 (< 48KB default)

    // loss scalar is the last output element
    warp_precompute_kernel<<<1, WT>>>(W1, b1, W2, b2, out + (out_size - 1));

    dim3 gridF(S / 32, F / FL, B);
    fused_kernel<<<gridF, 256, smem_bytes>>>(x, out);
}